// round 5
// baseline (speedup 1.0000x reference)
#include <cuda_runtime.h>
#include <math.h>

// Problem constants (B=32, H=W=56, C=384, win=7, shift=3, heads=12)
#define NROWS 100352            // B * H * W tokens
#define CDIM  384
#define QKVN  1152
#define HID   1536

// ---------------------------------------------------------------------------
// Scratch (static __device__ arrays; allocation APIs are forbidden)
// ---------------------------------------------------------------------------
__device__ float g_xw [(size_t)NROWS * CDIM];
__device__ float g_qkv[(size_t)NROWS * QKVN];
__device__ float g_ctx[(size_t)NROWS * CDIM];
__device__ float g_x2 [(size_t)NROWS * CDIM];
__device__ float g_y  [(size_t)NROWS * CDIM];
__device__ float g_h1 [(size_t)NROWS * HID];

__device__ __forceinline__ int shift_map(int r) {
    int b   = r / 3136;
    int rem = r - b * 3136;
    int w   = rem / 49;
    int n   = rem - w * 49;
    int nr  = n / 7, nc = n - nr * 7;
    int p = (w >> 3) * 7 + nr;
    int q = (w & 7)  * 7 + nc;
    p += 3; if (p >= 56) p -= 56;
    q += 3; if (q >= 56) q -= 56;
    return b * 3136 + p * 56 + q;
}

__device__ __forceinline__ float to_tf32(float x) {
    unsigned u;
    asm("cvt.rna.tf32.f32 %0, %1;" : "=r"(u) : "f"(x));
    return __uint_as_float(u);
}

__device__ __forceinline__ void mma_tf32(float* d, const unsigned* a, const unsigned* b) {
    asm volatile(
        "mma.sync.aligned.m16n8k8.row.col.f32.tf32.tf32.f32 "
        "{%0,%1,%2,%3}, {%4,%5,%6,%7}, {%8,%9}, {%0,%1,%2,%3};\n"
        : "+f"(d[0]), "+f"(d[1]), "+f"(d[2]), "+f"(d[3])
        : "r"(a[0]), "r"(a[1]), "r"(a[2]), "r"(a[3]), "r"(b[0]), "r"(b[1]));
}

// ---------------------------------------------------------------------------
// LayerNorm (one block per row of 384). gather=1 fuses roll(-3)+window-partition.
// ---------------------------------------------------------------------------
__global__ __launch_bounds__(128) void ln_kernel(
    const float* __restrict__ x, const float* __restrict__ gw,
    const float* __restrict__ gb, float* __restrict__ out, int gather)
{
    __shared__ float sh[4], sh2[4], bc[2];
    int r = blockIdx.x;
    int src = gather ? shift_map(r) : r;
    const float* xin = x + (size_t)src * CDIM;
    int t = threadIdx.x;
    float v0 = xin[t], v1 = xin[t + 128], v2 = xin[t + 256];
    float s  = v0 + v1 + v2;
    float ss = v0 * v0 + v1 * v1 + v2 * v2;
#pragma unroll
    for (int o = 16; o > 0; o >>= 1) {
        s  += __shfl_down_sync(0xffffffffu, s,  o);
        ss += __shfl_down_sync(0xffffffffu, ss, o);
    }
    int lane = t & 31, wid = t >> 5;
    if (lane == 0) { sh[wid] = s; sh2[wid] = ss; }
    __syncthreads();
    if (t == 0) {
        float S  = sh[0] + sh[1] + sh[2] + sh[3];
        float SS = sh2[0] + sh2[1] + sh2[2] + sh2[3];
        float mean = S * (1.0f / 384.0f);
        bc[0] = mean;
        bc[1] = rsqrtf(SS * (1.0f / 384.0f) - mean * mean + 1e-5f);
    }
    __syncthreads();
    float mean = bc[0], inv = bc[1];
    float* o = out + (size_t)r * CDIM;
    o[t]       = (v0 - mean) * inv * gw[t]       + gb[t];
    o[t + 128] = (v1 - mean) * inv * gw[t + 128] + gb[t + 128];
    o[t + 256] = (v2 - mean) * inv * gw[t + 256] + gb[t + 256];
}

// ---------------------------------------------------------------------------
// TF32 tensor-core GEMM: C[M,N] = A[M,K] @ B[K,N] (+ epilogue).
// CTA tile 256x128, BK=16, 8 warps in 4x2 grid, 64x64 warp tile
// (4x8 grid of m16n8k8). Double-buffered STATIC smem (48KB exactly):
//   As[2][256][16], XOR swizzle k' = k ^ (2*(m&7)); staging stores rotated
//       by (tid&3) -> both LDS and STS conflict-free (bank-verified).
//   Bs[2][16][128], XOR swizzle n' = n ^ (8*(k&3)); fragment LDS banks
//       8*((nt%4)^tig)+gr cover all 32; warp-uniform-row STS.128 stays a
//       permutation of the 128-float row -> conflict-free.
// EPI 0: +bias | 1: +bias,GELU | 2: +bias, scatter shift_map, +res | 3: +bias,+res
// ---------------------------------------------------------------------------
template<int EPI>
__global__ void __launch_bounds__(256, 1) tgemm(
    const float* __restrict__ A, const float* __restrict__ B,
    const float* __restrict__ bias, const float* __restrict__ res,
    float* __restrict__ C, int N, int K)
{
    __shared__ float As[2][256][16];   // 32 KB
    __shared__ float Bs[2][16][128];   // 16 KB

    int tid  = threadIdx.x;
    int warp = tid >> 5, lane = tid & 31;
    int wm = warp >> 1, wn = warp & 1;       // 4 x 2 warp grid
    int gr = lane >> 2, tig = lane & 3;
    int bM = blockIdx.y * 256, bN = blockIdx.x * 128;

    // staging maps
    int mA  = tid >> 2;          // 0..63 (rows mA + 64*r)
    int tq  = tid & 3;
    int kqA = tq * 4;            // 0,4,8,12
    int kB  = tid >> 5;          // 0..7 (and +8)
    int nqB = (tid & 31) * 4;    // 0..124
    int cS  = (mA & 7) * 2;      // A store swizzle const
    int cL  = gr * 2;            // A load  swizzle const
    int cB  = (kB & 3) * 8;      // B store swizzle const ((kB+8)&3 == kB&3)
    int cBl = tig * 8;           // B load  swizzle const

    float acc[4][8][4];
#pragma unroll
    for (int i = 0; i < 4; i++)
#pragma unroll
        for (int j = 0; j < 8; j++)
#pragma unroll
            for (int r = 0; r < 4; r++) acc[i][j][r] = 0.0f;

    float4 av[4], bv[2];

    auto load_tiles = [&](int kt) {
#pragma unroll
        for (int r = 0; r < 4; r++)
            av[r] = *(const float4*)(A + (size_t)(bM + mA + 64 * r) * K + kt * 16 + kqA);
        bv[0] = *(const float4*)(B + (size_t)(kt * 16 + kB)     * N + bN + nqB);
        bv[1] = *(const float4*)(B + (size_t)(kt * 16 + kB + 8) * N + bN + nqB);
    };
    auto store_tiles = [&](int buf) {
#pragma unroll
        for (int r = 0; r < 4; r++) {
            float* base = &As[buf][mA + 64 * r][0];
            float vv[4] = {av[r].x, av[r].y, av[r].z, av[r].w};
#pragma unroll
            for (int i = 0; i < 4; i++) {
                int j = (i + tq) & 3;          // rotation -> conflict-free STS
                base[(kqA + j) ^ cS] = to_tf32(vv[j]);
            }
        }
        float4 t;
        t.x = to_tf32(bv[0].x); t.y = to_tf32(bv[0].y); t.z = to_tf32(bv[0].z); t.w = to_tf32(bv[0].w);
        *(float4*)&Bs[buf][kB][nqB ^ cB] = t;
        t.x = to_tf32(bv[1].x); t.y = to_tf32(bv[1].y); t.z = to_tf32(bv[1].z); t.w = to_tf32(bv[1].w);
        *(float4*)&Bs[buf][kB + 8][nqB ^ cB] = t;
    };

    int KT = K >> 4;
    load_tiles(0);
    store_tiles(0);
    __syncthreads();

    for (int kt = 0; kt < KT; kt++) {
        int cur = kt & 1;
        if (kt + 1 < KT) load_tiles(kt + 1);

#pragma unroll
        for (int kk = 0; kk < 2; kk++) {
            int k0 = kk * 8;
            int x0 = (k0 + tig) ^ cL;          // swizzled k index (A)
            int x1 = x0 ^ 4;                   // k0+tig+4 (tig<4 so +4 == ^4)
            unsigned a[4][4], b[8][2];
#pragma unroll
            for (int mt = 0; mt < 4; mt++) {
                const float* ab = &As[cur][wm * 64 + mt * 16 + gr][0];
                a[mt][0] = __float_as_uint(ab[x0]);
                a[mt][1] = __float_as_uint(ab[128 + x0]);   // +8 rows
                a[mt][2] = __float_as_uint(ab[x1]);
                a[mt][3] = __float_as_uint(ab[128 + x1]);
            }
#pragma unroll
            for (int nt = 0; nt < 8; nt++) {
                int n = (wn * 64 + nt * 8 + gr) ^ cBl;      // swizzled n index (B)
                b[nt][0] = __float_as_uint(Bs[cur][k0 + tig    ][n]);
                b[nt][1] = __float_as_uint(Bs[cur][k0 + tig + 4][n]);  // (k+4)&3 == tig
            }
#pragma unroll
            for (int mt = 0; mt < 4; mt++)
#pragma unroll
                for (int nt = 0; nt < 8; nt++)
                    mma_tf32(acc[mt][nt], a[mt], b[nt]);
        }

        if (kt + 1 < KT) store_tiles(cur ^ 1);
        __syncthreads();
    }

    // Epilogue
#pragma unroll
    for (int mt = 0; mt < 4; mt++) {
        int r0 = bM + wm * 64 + mt * 16 + gr;
        int r1 = r0 + 8;
        int d0 = (EPI == 2) ? shift_map(r0) : r0;
        int d1 = (EPI == 2) ? shift_map(r1) : r1;
#pragma unroll
        for (int nt = 0; nt < 8; nt++) {
            int c0 = bN + wn * 64 + nt * 8 + tig * 2;
            float bb0 = bias[c0], bb1 = bias[c0 + 1];
            float v00 = acc[mt][nt][0] + bb0;
            float v01 = acc[mt][nt][1] + bb1;
            float v10 = acc[mt][nt][2] + bb0;
            float v11 = acc[mt][nt][3] + bb1;
            if (EPI == 1) {
                v00 = 0.5f * v00 * (1.0f + erff(v00 * 0.70710678118654752f));
                v01 = 0.5f * v01 * (1.0f + erff(v01 * 0.70710678118654752f));
                v10 = 0.5f * v10 * (1.0f + erff(v10 * 0.70710678118654752f));
                v11 = 0.5f * v11 * (1.0f + erff(v11 * 0.70710678118654752f));
            }
            if (EPI >= 2) {
                const float2 r0v = *(const float2*)(res + (size_t)d0 * N + c0);
                const float2 r1v = *(const float2*)(res + (size_t)d1 * N + c0);
                v00 += r0v.x; v01 += r0v.y;
                v10 += r1v.x; v11 += r1v.y;
            }
            *(float2*)(C + (size_t)d0 * N + c0) = make_float2(v00, v01);
            *(float2*)(C + (size_t)d1 * N + c0) = make_float2(v10, v11);
        }
    }
}

// ---------------------------------------------------------------------------
// Windowed attention: one block per (head, window). N=49, hd=32.
// ---------------------------------------------------------------------------
__global__ __launch_bounds__(256) void attn_kernel(
    const float* __restrict__ qkv, const float* __restrict__ rpb,
    float* __restrict__ ctx)
{
    __shared__ float qs[49][33], ks[49][33], vs[49][33], at[49][50];
    int head = blockIdx.x;
    int w    = blockIdx.y;
    int tid  = threadIdx.x;
    const float scale = 0.17677669529663687f;

    size_t base0 = (size_t)w * 49 * QKVN + head * 32;
    for (int e = tid; e < 49 * 32; e += 256) {
        int n = e >> 5, d = e & 31;
        size_t b = base0 + (size_t)n * QKVN + d;
        qs[n][d] = qkv[b] * scale;
        ks[n][d] = qkv[b + 384];
        vs[n][d] = qkv[b + 768];
    }
    int wloc = w & 63;
    int wh = wloc >> 3, wwi = wloc & 7;
    __syncthreads();

    for (int e = tid; e < 49 * 49; e += 256) {
        int n = e / 49, m = e - n * 49;
        float s = 0.0f;
#pragma unroll
        for (int d = 0; d < 32; d++) s = fmaf(qs[n][d], ks[m][d], s);
        int nr = n / 7, nc = n - nr * 7;
        int mr = m / 7, mc = m - mr * 7;
        s += rpb[((nr - mr + 6) * 13 + (nc - mc + 6)) * 12 + head];
        int rn = wh * 7 + nr, cn = wwi * 7 + nc;
        int rm = wh * 7 + mr, cm = wwi * 7 + mc;
        int gn = (rn < 49 ? 0 : (rn < 53 ? 1 : 2)) * 3 + (cn < 49 ? 0 : (cn < 53 ? 1 : 2));
        int gm = (rm < 49 ? 0 : (rm < 53 ? 1 : 2)) * 3 + (cm < 49 ? 0 : (cm < 53 ? 1 : 2));
        if (gn != gm) s -= 100.0f;
        at[n][m] = s;
    }
    __syncthreads();

    if (tid < 49) {
        float mx = -1e30f;
        for (int m = 0; m < 49; m++) mx = fmaxf(mx, at[tid][m]);
        float sum = 0.0f;
        for (int m = 0; m < 49; m++) {
            float e2 = expf(at[tid][m] - mx);
            at[tid][m] = e2;
            sum += e2;
        }
        float inv = 1.0f / sum;
        for (int m = 0; m < 49; m++) at[tid][m] *= inv;
    }
    __syncthreads();

    for (int e = tid; e < 49 * 32; e += 256) {
        int n = e >> 5, d = e & 31;
        float s = 0.0f;
#pragma unroll
        for (int m = 0; m < 49; m++) s = fmaf(at[n][m], vs[m][d], s);
        ctx[((size_t)w * 49 + n) * CDIM + head * 32 + d] = s;
    }
}

// ---------------------------------------------------------------------------
// Launch
// ---------------------------------------------------------------------------
extern "C" void kernel_launch(void* const* d_in, const int* in_sizes, int n_in,
                              void* d_out, int out_size)
{
    const float* x     = (const float*)d_in[0];
    const float* n1w   = (const float*)d_in[1];
    const float* n1b   = (const float*)d_in[2];
    const float* qkvw  = (const float*)d_in[3];
    const float* qkvb  = (const float*)d_in[4];
    const float* rpb   = (const float*)d_in[5];
    const float* projw = (const float*)d_in[6];
    const float* projb = (const float*)d_in[7];
    const float* n2w   = (const float*)d_in[8];
    const float* n2b   = (const float*)d_in[9];
    const float* fc1w  = (const float*)d_in[10];
    const float* fc1b  = (const float*)d_in[11];
    const float* fc2w  = (const float*)d_in[12];
    const float* fc2b  = (const float*)d_in[13];
    float* out = (float*)d_out;

    static bool init = false;
    static float *xw, *qkv, *ctx, *x2, *y, *h1;
    if (!init) {
        cudaGetSymbolAddress((void**)&xw,  g_xw);
        cudaGetSymbolAddress((void**)&qkv, g_qkv);
        cudaGetSymbolAddress((void**)&ctx, g_ctx);
        cudaGetSymbolAddress((void**)&x2,  g_x2);
        cudaGetSymbolAddress((void**)&y,   g_y);
        cudaGetSymbolAddress((void**)&h1,  g_h1);
        init = true;
    }

    // 1) LN1 + roll(-3,-3) + window partition (gather)
    ln_kernel<<<NROWS, 128>>>(x, n1w, n1b, xw, 1);
    // 2) fused QKV GEMM: [100352,384] @ [384,1152]
    tgemm<0><<<dim3(QKVN / 128, NROWS / 256), 256>>>(xw, qkvw, qkvb, nullptr, qkv, QKVN, CDIM);
    // 3) windowed attention per (head, window)
    attn_kernel<<<dim3(12, 2048), 256>>>(qkv, rpb, ctx);
    // 4) proj GEMM + window reverse + roll(+3,+3) + residual (scatter)
    tgemm<2><<<dim3(CDIM / 128, NROWS / 256), 256>>>(ctx, projw, projb, x, x2, CDIM, CDIM);
    // 5) LN2
    ln_kernel<<<NROWS, 128>>>(x2, n2w, n2b, y, 0);
    // 6) fc1 + GELU (exact erf)
    tgemm<1><<<dim3(HID / 128, NROWS / 256), 256>>>(y, fc1w, fc1b, nullptr, h1, HID, CDIM);
    // 7) fc2 + final residual
    tgemm<3><<<dim3(CDIM / 128, NROWS / 256), 256>>>(h1, fc2w, fc2b, x2, out, CDIM, HID);
}

// round 9
// speedup vs baseline: 1.1436x; 1.1436x over previous
#include <cuda_runtime.h>
#include <math.h>

// Problem constants (B=32, H=W=56, C=384, win=7, shift=3, heads=12)
#define NROWS 100352            // B * H * W tokens
#define CDIM  384
#define QKVN  1152
#define HID   1536

// ---------------------------------------------------------------------------
// Scratch (static __device__ arrays; allocation APIs are forbidden)
// ---------------------------------------------------------------------------
__device__ float g_xw [(size_t)NROWS * CDIM];
__device__ float g_qkv[(size_t)NROWS * QKVN];
__device__ float g_ctx[(size_t)NROWS * CDIM];
__device__ float g_x2 [(size_t)NROWS * CDIM];
__device__ float g_y  [(size_t)NROWS * CDIM];
__device__ float g_h1 [(size_t)NROWS * HID];
__device__ float g_wt [(size_t)HID * CDIM];   // rounded-weight scratch (max 1536*384)

__device__ __forceinline__ int shift_map(int r) {
    int b   = r / 3136;
    int rem = r - b * 3136;
    int w   = rem / 49;
    int n   = rem - w * 49;
    int nr  = n / 7, nc = n - nr * 7;
    int p = (w >> 3) * 7 + nr;
    int q = (w & 7)  * 7 + nc;
    p += 3; if (p >= 56) p -= 56;
    q += 3; if (q >= 56) q -= 56;
    return b * 3136 + p * 56 + q;
}

__device__ __forceinline__ float to_tf32(float x) {
    unsigned u;
    asm("cvt.rna.tf32.f32 %0, %1;" : "=r"(u) : "f"(x));
    return __uint_as_float(u);
}

__device__ __forceinline__ void mma_tf32(float* d, const unsigned* a, const unsigned* b) {
    asm volatile(
        "mma.sync.aligned.m16n8k8.row.col.f32.tf32.tf32.f32 "
        "{%0,%1,%2,%3}, {%4,%5,%6,%7}, {%8,%9}, {%0,%1,%2,%3};\n"
        : "+f"(d[0]), "+f"(d[1]), "+f"(d[2]), "+f"(d[3])
        : "r"(a[0]), "r"(a[1]), "r"(a[2]), "r"(a[3]), "r"(b[0]), "r"(b[1]));
}

__device__ __forceinline__ unsigned smem_u32(const void* p) {
    unsigned a;
    asm("{ .reg .u64 t; cvta.to.shared.u64 t, %1; cvt.u32.u64 %0, t; }" : "=r"(a) : "l"(p));
    return a;
}
#define CP_ASYNC16(dst, src) \
    asm volatile("cp.async.cg.shared.global [%0], [%1], 16;" :: "r"(dst), "l"(src) : "memory")
#define CP_COMMIT()  asm volatile("cp.async.commit_group;" ::: "memory")
#define CP_WAIT1()   asm volatile("cp.async.wait_group 1;" ::: "memory")

// ---------------------------------------------------------------------------
// LayerNorm (one block per row of 384). gather=1 fuses roll(-3)+window-partition.
// Output is tf32-rounded (it only ever feeds a GEMM A-operand).
// ---------------------------------------------------------------------------
__global__ __launch_bounds__(128) void ln_kernel(
    const float* __restrict__ x, const float* __restrict__ gw,
    const float* __restrict__ gb, float* __restrict__ out, int gather)
{
    __shared__ float sh[4], sh2[4], bc[2];
    int r = blockIdx.x;
    int src = gather ? shift_map(r) : r;
    const float* xin = x + (size_t)src * CDIM;
    int t = threadIdx.x;
    float v0 = xin[t], v1 = xin[t + 128], v2 = xin[t + 256];
    float s  = v0 + v1 + v2;
    float ss = v0 * v0 + v1 * v1 + v2 * v2;
#pragma unroll
    for (int o = 16; o > 0; o >>= 1) {
        s  += __shfl_down_sync(0xffffffffu, s,  o);
        ss += __shfl_down_sync(0xffffffffu, ss, o);
    }
    int lane = t & 31, wid = t >> 5;
    if (lane == 0) { sh[wid] = s; sh2[wid] = ss; }
    __syncthreads();
    if (t == 0) {
        float S  = sh[0] + sh[1] + sh[2] + sh[3];
        float SS = sh2[0] + sh2[1] + sh2[2] + sh2[3];
        float mean = S * (1.0f / 384.0f);
        bc[0] = mean;
        bc[1] = rsqrtf(SS * (1.0f / 384.0f) - mean * mean + 1e-5f);
    }
    __syncthreads();
    float mean = bc[0], inv = bc[1];
    float* o = out + (size_t)r * CDIM;
    o[t]       = to_tf32((v0 - mean) * inv * gw[t]       + gb[t]);
    o[t + 128] = to_tf32((v1 - mean) * inv * gw[t + 128] + gb[t + 128]);
    o[t + 256] = to_tf32((v2 - mean) * inv * gw[t + 256] + gb[t + 256]);
}

// ---------------------------------------------------------------------------
// Elementwise tf32 rounding of a weight matrix (layout preserved).
// ---------------------------------------------------------------------------
__global__ __launch_bounds__(256) void round_w(
    const float* __restrict__ w, float* __restrict__ o, int n)
{
    int i = blockIdx.x * 256 + threadIdx.x;
    if (i < n) o[i] = to_tf32(w[i]);
}

// ---------------------------------------------------------------------------
// TF32 mma.sync GEMM with cp.async 3-stage pipeline.
// C[M,N] = A[M,K] @ B[K,N] (+ epilogue). All inputs pre-tf32-rounded.
// CTA tile 128x128, BK=16, 8 warps in 2x4 grid, 64x32 warp tile
// (4x4 m16n8k8). 48KB static smem, 3 stages of (A 8KB + B 8KB).
//   As[s][128][16], 16B-chunk swizzle c' = c ^ ((m>>1)&3)   -> LDS conflict-free
//   Bs[s][16][128], 16B-chunk swizzle c' = c ^ (2*(k&3))    -> LDS conflict-free
// Pipeline: wait_group 1 at iter kt guarantees stage kt landed; stage(kt+2)
// overwrites buffer (kt-1)%3 whose readers all passed this iter's barrier.
// EPI 0: +bias | 1: +bias,GELU,round | 2: +bias, scatter shift_map, +res | 3: +bias,+res
// ---------------------------------------------------------------------------
template<int EPI>
__global__ void __launch_bounds__(256, 2) pgemm(
    const float* __restrict__ A, const float* __restrict__ B,
    const float* __restrict__ bias, const float* __restrict__ res,
    float* __restrict__ C, int N, int K)
{
    __shared__ float As[3][128][16];   // 24 KB
    __shared__ float Bs[3][16][128];   // 24 KB

    int tid  = threadIdx.x;
    int warp = tid >> 5, lane = tid & 31;
    int wm = warp >> 2, wn = warp & 3;        // 2 x 4 warp grid
    int gr = lane >> 2, tig = lane & 3;
    int g2 = gr >> 1;
    int bM = blockIdx.y * 128, bN = blockIdx.x * 128;

    unsigned asmb = smem_u32(&As[0][0][0]);
    unsigned bsmb = smem_u32(&Bs[0][0][0]);

    // staging maps (per thread: 2 A-chunks + 2 B-chunks of 16B)
    int mA  = tid >> 1;                 // 0..127
    int ca0 = (tid & 1) * 2;            // A chunks ca0, ca0+1 (of 4)
    int kB  = tid >> 4;                 // 0..15
    int cb0 = (tid & 15) * 2;           // B chunks cb0, cb0+1 (of 32)
    int swA = (mA >> 1) & 3;
    int swB = (kB & 3) * 2;

    const float* Abase = A + (size_t)(bM + mA) * K;

    float acc[4][4][4];
#pragma unroll
    for (int i = 0; i < 4; i++)
#pragma unroll
        for (int j = 0; j < 4; j++)
#pragma unroll
            for (int r = 0; r < 4; r++) acc[i][j][r] = 0.0f;

    auto stage = [&](int kt, int buf) {
        const float* a0 = Abase + kt * 16;
        unsigned ad = asmb + buf * 8192 + mA * 64;
#pragma unroll
        for (int i = 0; i < 2; i++) {
            int ca = ca0 + i;
            CP_ASYNC16(ad + ((ca ^ swA) << 4), a0 + ca * 4);
        }
        const float* b0 = B + (size_t)(kt * 16 + kB) * N + bN;
        unsigned bd = bsmb + buf * 8192 + kB * 512;
#pragma unroll
        for (int i = 0; i < 2; i++) {
            int cb = cb0 + i;
            CP_ASYNC16(bd + ((cb ^ swB) << 4), b0 + cb * 4);
        }
        CP_COMMIT();
    };

    int KT = K >> 4;
    stage(0, 0);
    stage(1, 1);

    for (int kt = 0; kt < KT; kt++) {
        int cur = kt - (kt / 3) * 3;        // kt % 3
        CP_WAIT1();
        __syncthreads();
        if (kt + 2 < KT) {
            int nb = cur + 2; if (nb >= 3) nb -= 3;
            stage(kt + 2, nb);
        }

        const float* asp = &As[cur][0][0];
        const float* bsp = &Bs[cur][0][0];
#pragma unroll
        for (int kk = 0; kk < 2; kk++) {
            int k04 = kk * 2;                       // k0 >> 2  (k0 = 8*kk)
            int x0 = ((k04     ) ^ g2) * 4 + tig;
            int x1 = ((k04 ^ 1 ) ^ g2) * 4 + tig;   // (k0>>2)+1 == ^1 (k04 even)
            unsigned a[4][4], b[4][2];
#pragma unroll
            for (int mt = 0; mt < 4; mt++) {
                const float* ar = asp + (wm * 64 + mt * 16 + gr) * 16;
                a[mt][0] = __float_as_uint(ar[x0]);
                a[mt][1] = __float_as_uint(ar[128 + x0]);   // +8 rows
                a[mt][2] = __float_as_uint(ar[x1]);
                a[mt][3] = __float_as_uint(ar[128 + x1]);
            }
            const float* br = bsp + (kk * 8 + tig) * 128;
#pragma unroll
            for (int nt = 0; nt < 4; nt++) {
                int n = (wn * 32 + nt * 8 + gr) ^ (tig * 8);
                b[nt][0] = __float_as_uint(br[n]);
                b[nt][1] = __float_as_uint(br[512 + n]);    // +4 k-rows
            }
#pragma unroll
            for (int mt = 0; mt < 4; mt++)
#pragma unroll
                for (int nt = 0; nt < 4; nt++)
                    mma_tf32(acc[mt][nt], a[mt], b[nt]);
        }
    }

    // Epilogue
#pragma unroll
    for (int mt = 0; mt < 4; mt++) {
        int r0 = bM + wm * 64 + mt * 16 + gr;
        int r1 = r0 + 8;
        int d0 = (EPI == 2) ? shift_map(r0) : r0;
        int d1 = (EPI == 2) ? shift_map(r1) : r1;
#pragma unroll
        for (int nt = 0; nt < 4; nt++) {
            int c0 = bN + wn * 32 + nt * 8 + tig * 2;
            float bb0 = bias[c0], bb1 = bias[c0 + 1];
            float v00 = acc[mt][nt][0] + bb0;
            float v01 = acc[mt][nt][1] + bb1;
            float v10 = acc[mt][nt][2] + bb0;
            float v11 = acc[mt][nt][3] + bb1;
            if (EPI == 1) {
                v00 = to_tf32(0.5f * v00 * (1.0f + erff(v00 * 0.70710678118654752f)));
                v01 = to_tf32(0.5f * v01 * (1.0f + erff(v01 * 0.70710678118654752f)));
                v10 = to_tf32(0.5f * v10 * (1.0f + erff(v10 * 0.70710678118654752f)));
                v11 = to_tf32(0.5f * v11 * (1.0f + erff(v11 * 0.70710678118654752f)));
            }
            if (EPI >= 2) {
                const float2 r0v = *(const float2*)(res + (size_t)d0 * N + c0);
                const float2 r1v = *(const float2*)(res + (size_t)d1 * N + c0);
                v00 += r0v.x; v01 += r0v.y;
                v10 += r1v.x; v11 += r1v.y;
            }
            *(float2*)(C + (size_t)d0 * N + c0) = make_float2(v00, v01);
            *(float2*)(C + (size_t)d1 * N + c0) = make_float2(v10, v11);
        }
    }
}

// ---------------------------------------------------------------------------
// Windowed attention: one block per (head, window). N=49, hd=32.
// Output tf32-rounded (feeds proj GEMM A-operand only).
// ---------------------------------------------------------------------------
__global__ __launch_bounds__(256) void attn_kernel(
    const float* __restrict__ qkv, const float* __restrict__ rpb,
    float* __restrict__ ctx)
{
    __shared__ float qs[49][33], ks[49][33], vs[49][33], at[49][50];
    int head = blockIdx.x;
    int w    = blockIdx.y;
    int tid  = threadIdx.x;
    const float scale = 0.17677669529663687f;

    size_t base0 = (size_t)w * 49 * QKVN + head * 32;
    for (int e = tid; e < 49 * 32; e += 256) {
        int n = e >> 5, d = e & 31;
        size_t b = base0 + (size_t)n * QKVN + d;
        qs[n][d] = qkv[b] * scale;
        ks[n][d] = qkv[b + 384];
        vs[n][d] = qkv[b + 768];
    }
    int wloc = w & 63;
    int wh = wloc >> 3, wwi = wloc & 7;
    __syncthreads();

    for (int e = tid; e < 49 * 49; e += 256) {
        int n = e / 49, m = e - n * 49;
        float s = 0.0f;
#pragma unroll
        for (int d = 0; d < 32; d++) s = fmaf(qs[n][d], ks[m][d], s);
        int nr = n / 7, nc = n - nr * 7;
        int mr = m / 7, mc = m - mr * 7;
        s += rpb[((nr - mr + 6) * 13 + (nc - mc + 6)) * 12 + head];
        int rn = wh * 7 + nr, cn = wwi * 7 + nc;
        int rm = wh * 7 + mr, cm = wwi * 7 + mc;
        int gn = (rn < 49 ? 0 : (rn < 53 ? 1 : 2)) * 3 + (cn < 49 ? 0 : (cn < 53 ? 1 : 2));
        int gm = (rm < 49 ? 0 : (rm < 53 ? 1 : 2)) * 3 + (cm < 49 ? 0 : (cm < 53 ? 1 : 2));
        if (gn != gm) s -= 100.0f;
        at[n][m] = s;
    }
    __syncthreads();

    if (tid < 49) {
        float mx = -1e30f;
        for (int m = 0; m < 49; m++) mx = fmaxf(mx, at[tid][m]);
        float sum = 0.0f;
        for (int m = 0; m < 49; m++) {
            float e2 = expf(at[tid][m] - mx);
            at[tid][m] = e2;
            sum += e2;
        }
        float inv = 1.0f / sum;
        for (int m = 0; m < 49; m++) at[tid][m] *= inv;
    }
    __syncthreads();

    for (int e = tid; e < 49 * 32; e += 256) {
        int n = e >> 5, d = e & 31;
        float s = 0.0f;
#pragma unroll
        for (int m = 0; m < 49; m++) s = fmaf(at[n][m], vs[m][d], s);
        ctx[((size_t)w * 49 + n) * CDIM + head * 32 + d] = to_tf32(s);
    }
}

// ---------------------------------------------------------------------------
// Launch
// ---------------------------------------------------------------------------
extern "C" void kernel_launch(void* const* d_in, const int* in_sizes, int n_in,
                              void* d_out, int out_size)
{
    const float* x     = (const float*)d_in[0];
    const float* n1w   = (const float*)d_in[1];
    const float* n1b   = (const float*)d_in[2];
    const float* qkvw  = (const float*)d_in[3];
    const float* qkvb  = (const float*)d_in[4];
    const float* rpb   = (const float*)d_in[5];
    const float* projw = (const float*)d_in[6];
    const float* projb = (const float*)d_in[7];
    const float* n2w   = (const float*)d_in[8];
    const float* n2b   = (const float*)d_in[9];
    const float* fc1w  = (const float*)d_in[10];
    const float* fc1b  = (const float*)d_in[11];
    const float* fc2w  = (const float*)d_in[12];
    const float* fc2b  = (const float*)d_in[13];
    float* out = (float*)d_out;

    static bool init = false;
    static float *xw, *qkv, *ctx, *x2, *y, *h1, *wt;
    if (!init) {
        cudaGetSymbolAddress((void**)&xw,  g_xw);
        cudaGetSymbolAddress((void**)&qkv, g_qkv);
        cudaGetSymbolAddress((void**)&ctx, g_ctx);
        cudaGetSymbolAddress((void**)&x2,  g_x2);
        cudaGetSymbolAddress((void**)&y,   g_y);
        cudaGetSymbolAddress((void**)&h1,  g_h1);
        cudaGetSymbolAddress((void**)&wt,  g_wt);
        init = true;
    }

    // 1) LN1 + roll(-3,-3) + window partition (gather), tf32-rounded out
    ln_kernel<<<NROWS, 128>>>(x, n1w, n1b, xw, 1);
    // 2) fused QKV GEMM: [100352,384] @ [384,1152]
    round_w<<<(CDIM * QKVN + 255) / 256, 256>>>(qkvw, wt, CDIM * QKVN);
    pgemm<0><<<dim3(QKVN / 128, NROWS / 128), 256>>>(xw, wt, qkvb, nullptr, qkv, QKVN, CDIM);
    // 3) windowed attention per (head, window), tf32-rounded out
    attn_kernel<<<dim3(12, 2048), 256>>>(qkv, rpb, ctx);
    // 4) proj GEMM + window reverse + roll(+3,+3) + residual (scatter)
    round_w<<<(CDIM * CDIM + 255) / 256, 256>>>(projw, wt, CDIM * CDIM);
    pgemm<2><<<dim3(CDIM / 128, NROWS / 128), 256>>>(ctx, wt, projb, x, x2, CDIM, CDIM);
    // 5) LN2, tf32-rounded out
    ln_kernel<<<NROWS, 128>>>(x2, n2w, n2b, y, 0);
    // 6) fc1 + GELU (exact erf), tf32-rounded out
    round_w<<<(CDIM * HID + 255) / 256, 256>>>(fc1w, wt, CDIM * HID);
    pgemm<1><<<dim3(HID / 128, NROWS / 128), 256>>>(y, wt, fc1b, nullptr, h1, HID, CDIM);
    // 7) fc2 + final residual
    round_w<<<(HID * CDIM + 255) / 256, 256>>>(fc2w, wt, HID * CDIM);
    pgemm<3><<<dim3(CDIM / 128, NROWS / 128), 256>>>(h1, wt, fc2b, x2, out, CDIM, HID);
}